// round 2
// baseline (speedup 1.0000x reference)
#include <cuda_runtime.h>
#include <math.h>

#define W_ 192
#define H_ 192
#define D_ 160
#define CHUNK 80
#define NPLANES (CHUNK + 4)
#define NBLOCKS (6 * 12 * 4)

// Scratch accumulators (device globals are zero-initialized at module load;
// the last block resets them each run so graph replays stay deterministic).
__device__ double   g_acc;
__device__ unsigned g_cnt;

__global__ void __launch_bounds__(512, 2)
lncc_k(const float* __restrict__ src, const float* __restrict__ tgt,
       float* __restrict__ out)
{
    // tile[img][haloRow(20)][col(36 pad 40)]
    __shared__ float tile[2][20][40];
    // rs[ch][haloRow(20)][x(32)] : x-direction 5-tap sums
    __shared__ float rs[5][20][32];
    __shared__ float wsum[16];

    const int tx  = threadIdx.x;
    const int ty  = threadIdx.y;
    const int tid = ty * 32 + tx;
    const int x0  = blockIdx.x * 32;
    const int y0  = blockIdx.y * 16;
    const int b   = blockIdx.z >> 1;
    const int z0  = (blockIdx.z & 1) * CHUNK;

    const float* baseS = src + (size_t)b * (D_ * H_ * W_);
    const float* baseT = tgt + (size_t)b * (D_ * H_ * W_);

    // ---- per-thread load slots: 36x20 halo tile, both images per slot ----
    // rows: r = ty + 16k (k=1 only ty<4); cols: c = tx + 32m (m=1 only tx<4)
    int goff[4];
    int soff[4];
    unsigned flags = 0;  // bit sl: gmem in-range; bit sl+8: slot used
    #pragma unroll
    for (int k2 = 0; k2 < 2; k2++) {
        #pragma unroll
        for (int m = 0; m < 2; m++) {
            const int sl = k2 * 2 + m;
            goff[sl] = 0; soff[sl] = 0;
            const bool slotv = (k2 == 0 || ty < 4) && (m == 0 || tx < 4);
            if (slotv) {
                const int r = ty + 16 * k2;
                const int c = tx + 32 * m;
                soff[sl] = r * 40 + c;
                flags |= 1u << (sl + 8);
                const int gy = y0 + r - 2;
                const int gx = x0 + c - 2;
                if ((unsigned)gy < (unsigned)H_ && (unsigned)gx < (unsigned)W_) {
                    flags |= 1u << sl;
                    goff[sl] = gy * W_ + gx;
                }
            }
        }
    }

    float pfs[4], pft[4];
    auto issue_loads = [&](int zp) {
        const bool zin  = (zp >= 0) && (zp < D_);
        const int pbase = zp * (H_ * W_);
        #pragma unroll
        for (int sl = 0; sl < 4; sl++) {
            float vs = 0.f, vt = 0.f;
            if (zin && (flags & (1u << sl))) {
                vs = __ldg(baseS + pbase + goff[sl]);
                vt = __ldg(baseT + pbase + goff[sl]);
            }
            pfs[sl] = vs; pft[sl] = vt;
        }
    };
    auto store_tiles = [&]() {
        float* tf = &tile[0][0][0];
        #pragma unroll
        for (int sl = 0; sl < 4; sl++)
            if (flags & (1u << (sl + 8))) {
                tf[soff[sl]]       = pfs[sl];
                tf[800 + soff[sl]] = pft[sl];
            }
    };

    // ---- register ring buffer for z-direction 5-tap sums (1 px/thread) ----
    float ring[5][5];
    float run[5];
    #pragma unroll
    for (int s = 0; s < 5; s++)
        #pragma unroll
        for (int c = 0; c < 5; c++) ring[s][c] = 0.f;
    #pragma unroll
    for (int c = 0; c < 5; c++) run[c] = 0.f;

    float acc = 0.f;
    const int zstart = z0 - 2;

    issue_loads(zstart);

    for (int basep = 0; basep < NPLANES; basep += 5) {
        #pragma unroll
        for (int s = 0; s < 5; s++) {            // compile-time ring slot
            const int ip = basep + s;
            if (ip >= NPLANES) break;
            const int zp = zstart + ip;

            __syncthreads();                     // prev plane fully consumed
            store_tiles();
            issue_loads(zp + 1);                 // prefetch next plane
            __syncthreads();                     // tile ready

            // ---- x-direction sliding 5-tap sums: 20 rows x 8 groups ----
            if (tid < 160) {
                const int r  = tid >> 3;
                const int x4 = (tid & 7) << 2;
                const float* rowS = &tile[0][r][x4];
                const float* rowT = &tile[1][r][x4];
                float4 a0 = *(const float4*)(rowS);
                float4 a1 = *(const float4*)(rowS + 4);
                float4 b0 = *(const float4*)(rowT);
                float4 b1 = *(const float4*)(rowT + 4);
                float sc[8] = {a0.x,a0.y,a0.z,a0.w,a1.x,a1.y,a1.z,a1.w};
                float tc[8] = {b0.x,b0.y,b0.z,b0.w,b1.x,b1.y,b1.z,b1.w};

                // channel-pair-wise to keep register peak low
                {
                    float S0=0.f, T0=0.f;
                    #pragma unroll
                    for (int j = 0; j < 5; j++) { S0 += sc[j]; T0 += tc[j]; }
                    float Sv[4], Tv[4];
                    Sv[0]=S0; Tv[0]=T0;
                    #pragma unroll
                    for (int w = 1; w < 4; w++) {
                        Sv[w] = Sv[w-1] - sc[w-1] + sc[w+4];
                        Tv[w] = Tv[w-1] - tc[w-1] + tc[w+4];
                    }
                    *(float4*)&rs[0][r][x4] = make_float4(Sv[0],Sv[1],Sv[2],Sv[3]);
                    *(float4*)&rs[1][r][x4] = make_float4(Tv[0],Tv[1],Tv[2],Tv[3]);
                }
                {
                    float SS0=0.f, TT0=0.f;
                    #pragma unroll
                    for (int j = 0; j < 5; j++) {
                        SS0 = fmaf(sc[j], sc[j], SS0);
                        TT0 = fmaf(tc[j], tc[j], TT0);
                    }
                    float SSv[4], TTv[4];
                    SSv[0]=SS0; TTv[0]=TT0;
                    #pragma unroll
                    for (int w = 1; w < 4; w++) {
                        SSv[w] = SSv[w-1] - sc[w-1]*sc[w-1] + sc[w+4]*sc[w+4];
                        TTv[w] = TTv[w-1] - tc[w-1]*tc[w-1] + tc[w+4]*tc[w+4];
                    }
                    *(float4*)&rs[2][r][x4] = make_float4(SSv[0],SSv[1],SSv[2],SSv[3]);
                    *(float4*)&rs[3][r][x4] = make_float4(TTv[0],TTv[1],TTv[2],TTv[3]);
                }
                {
                    float ST0=0.f;
                    #pragma unroll
                    for (int j = 0; j < 5; j++) ST0 = fmaf(sc[j], tc[j], ST0);
                    float STv[4];
                    STv[0]=ST0;
                    #pragma unroll
                    for (int w = 1; w < 4; w++)
                        STv[w] = STv[w-1] - sc[w-1]*tc[w-1] + sc[w+4]*tc[w+4];
                    *(float4*)&rs[4][r][x4] = make_float4(STv[0],STv[1],STv[2],STv[3]);
                }
            }
            __syncthreads();                     // rs ready

            // ---- y-direction 5-tap sum + z ring update, 1 px/thread ----
            const int zo = zp - 2;
            #pragma unroll
            for (int c = 0; c < 5; c++) {
                float n = ((rs[c][ty+0][tx] + rs[c][ty+1][tx])
                         + (rs[c][ty+2][tx] + rs[c][ty+3][tx]))
                         +  rs[c][ty+4][tx];
                run[c]    += n - ring[s][c];
                ring[s][c] = n;
            }

            if (zo >= z0 && zo < z0 + CHUNK) {
                const float inv = 1.f / 125.f;
                float sm = run[0] * inv;
                float tm = run[1] * inv;
                float sv = fmaf(-sm, sm, run[2] * inv);
                float tv = fmaf(-tm, tm, run[3] * inv);
                float cr = fmaf(-sm, tm, run[4] * inv);
                float den = fmaf(sv, tv, 1e-5f);
                acc += __fdividef(cr * cr, den);
            }
        }
    }

    // ---- block reduction ----
    #pragma unroll
    for (int o = 16; o > 0; o >>= 1)
        acc += __shfl_xor_sync(0xffffffffu, acc, o);
    if ((tid & 31) == 0) wsum[tid >> 5] = acc;
    __syncthreads();

    // ---- grid reduction + last-block finalize (no extra kernels) ----
    if (tid == 0) {
        float bsum = 0.f;
        #pragma unroll
        for (int i = 0; i < 16; i++) bsum += wsum[i];
        atomicAdd(&g_acc, (double)bsum);
        __threadfence();
        unsigned done = atomicAdd(&g_cnt, 1u);
        if (done == NBLOCKS - 1) {
            double total = atomicAdd(&g_acc, 0.0);  // fenced read
            const double n = 2.0 * 160.0 * 192.0 * 192.0;
            float loss = (float)(1.0 - total / n);
            if (isnan(loss) || isinf(loss)) loss = 1.0f;
            out[0] = loss;
            // reset for the next graph replay
            *((volatile double*)&g_acc)   = 0.0;
            *((volatile unsigned*)&g_cnt) = 0u;
        }
    }
}

extern "C" void kernel_launch(void* const* d_in, const int* in_sizes, int n_in,
                              void* d_out, int out_size)
{
    (void)in_sizes; (void)n_in; (void)out_size;
    const float* src = (const float*)d_in[0];
    const float* tgt = (const float*)d_in[1];

    lncc_k<<<dim3(W_ / 32, H_ / 16, 2 * (D_ / CHUNK)), dim3(32, 16)>>>(
        src, tgt, (float*)d_out);
}

// round 3
// speedup vs baseline: 1.7459x; 1.7459x over previous
#include <cuda_runtime.h>
#include <math.h>

#define W_ 192
#define H_ 192
#define D_ 160
#define CHUNK 80
#define NPLANES (CHUNK + 4)
#define NBLOCKS (6 * 12 * 4)

// Scratch accumulators (device globals; last block resets them each run so
// graph replays stay deterministic).
__device__ double   g_acc;
__device__ unsigned g_cnt;

__global__ void __launch_bounds__(256, 2)
lncc_k(const float* __restrict__ src, const float* __restrict__ tgt,
       float* __restrict__ out)
{
    // Double-buffered input tile: [buf][img][haloRow(20)][col(36 pad 40)]
    __shared__ float tile[2][2][20][40];
    // rs[ch][haloRow(20)][x(32)] : x-direction 5-tap sums
    __shared__ float rs[5][20][32];
    __shared__ float wsum[8];

    const int tx  = threadIdx.x;
    const int ty  = threadIdx.y;            // 0..7
    const int tid = ty * 32 + tx;
    const int x0  = blockIdx.x * 32;
    const int y0  = blockIdx.y * 16;
    const int b   = blockIdx.z >> 1;
    const int z0  = (blockIdx.z & 1) * CHUNK;

    const float* baseS = src + (size_t)b * (D_ * H_ * W_);
    const float* baseT = tgt + (size_t)b * (D_ * H_ * W_);

    // ---- per-thread load slots: 36 x 20 halo tile, both images per slot ----
    // rows: r = ty + 8k (k=2 only ty<4); cols: c = tx + 32m (m=1 only tx<4)
    int goff[6];
    int soff[6];
    unsigned flags = 0;  // bit sl: gmem in-range; bit sl+8: slot used
    #pragma unroll
    for (int k = 0; k < 3; k++) {
        #pragma unroll
        for (int m = 0; m < 2; m++) {
            const int sl = k * 2 + m;
            goff[sl] = 0; soff[sl] = 0;
            const int r = ty + 8 * k;
            const int c = tx + 32 * m;
            const bool slotv = (r < 20) && (m == 0 || tx < 4);
            if (slotv) {
                soff[sl] = r * 40 + c;
                flags |= 1u << (sl + 8);
                const int gy = y0 + r - 2;
                const int gx = x0 + c - 2;
                if ((unsigned)gy < (unsigned)H_ && (unsigned)gx < (unsigned)W_) {
                    flags |= 1u << sl;
                    goff[sl] = gy * W_ + gx;
                }
            }
        }
    }

    float pfs[6], pft[6];
    auto issue_loads = [&](int zp) {
        const bool zin  = (zp >= 0) && (zp < D_);
        const int pbase = zp * (H_ * W_);
        #pragma unroll
        for (int sl = 0; sl < 6; sl++) {
            float vs = 0.f, vt = 0.f;
            if (zin && (flags & (1u << sl))) {
                vs = __ldg(baseS + pbase + goff[sl]);
                vt = __ldg(baseT + pbase + goff[sl]);
            }
            pfs[sl] = vs; pft[sl] = vt;
        }
    };
    auto store_tiles = [&](int buf) {
        float* tf = &tile[buf][0][0][0];
        #pragma unroll
        for (int sl = 0; sl < 6; sl++)
            if (flags & (1u << (sl + 8))) {
                tf[soff[sl]]       = pfs[sl];
                tf[800 + soff[sl]] = pft[sl];
            }
    };

    // ---- register ring buffer for z-direction 5-tap sums (2 px/thread) ----
    float ring[5][2][5];
    float run[2][5];
    #pragma unroll
    for (int s = 0; s < 5; s++)
        #pragma unroll
        for (int p = 0; p < 2; p++)
            #pragma unroll
            for (int c = 0; c < 5; c++) ring[s][p][c] = 0.f;
    #pragma unroll
    for (int p = 0; p < 2; p++)
        #pragma unroll
        for (int c = 0; c < 5; c++) run[p][c] = 0.f;

    float acc = 0.f;
    const int zstart = z0 - 2;
    const int yb = 2 * ty;

    issue_loads(zstart);

    for (int basep = 0; basep < NPLANES; basep += 5) {
        #pragma unroll
        for (int s = 0; s < 5; s++) {            // compile-time ring slot
            const int ip = basep + s;
            if (ip >= NPLANES) break;
            const int zp  = zstart + ip;
            const int buf = ip & 1;

            // store current plane into its buffer; prefetch next plane.
            // Safe without a pre-barrier: tile[buf] was last read in the
            // x-phase two planes ago, fully fenced by the barriers since.
            store_tiles(buf);
            issue_loads(zp + 1);
            __syncthreads();   // tile[buf] ready AND rs from prev plane consumed

            // ---- x-direction sliding 5-tap sums: 20 rows x 8 groups ----
            if (tid < 160) {
                const int r  = tid >> 3;
                const int x4 = (tid & 7) << 2;
                const float* rowS = &tile[buf][0][r][x4];
                const float* rowT = &tile[buf][1][r][x4];
                float4 a0 = *(const float4*)(rowS);
                float4 a1 = *(const float4*)(rowS + 4);
                float4 b0 = *(const float4*)(rowT);
                float4 b1 = *(const float4*)(rowT + 4);
                float sc[8] = {a0.x,a0.y,a0.z,a0.w,a1.x,a1.y,a1.z,a1.w};
                float tc[8] = {b0.x,b0.y,b0.z,b0.w,b1.x,b1.y,b1.z,b1.w};

                // channel-pair-wise to keep register peak low
                {
                    float S0=0.f, T0=0.f;
                    #pragma unroll
                    for (int j = 0; j < 5; j++) { S0 += sc[j]; T0 += tc[j]; }
                    float Sv[4], Tv[4];
                    Sv[0]=S0; Tv[0]=T0;
                    #pragma unroll
                    for (int w = 1; w < 4; w++) {
                        Sv[w] = Sv[w-1] - sc[w-1] + sc[w+4];
                        Tv[w] = Tv[w-1] - tc[w-1] + tc[w+4];
                    }
                    *(float4*)&rs[0][r][x4] = make_float4(Sv[0],Sv[1],Sv[2],Sv[3]);
                    *(float4*)&rs[1][r][x4] = make_float4(Tv[0],Tv[1],Tv[2],Tv[3]);
                }
                {
                    float SS0=0.f, TT0=0.f;
                    #pragma unroll
                    for (int j = 0; j < 5; j++) {
                        SS0 = fmaf(sc[j], sc[j], SS0);
                        TT0 = fmaf(tc[j], tc[j], TT0);
                    }
                    float SSv[4], TTv[4];
                    SSv[0]=SS0; TTv[0]=TT0;
                    #pragma unroll
                    for (int w = 1; w < 4; w++) {
                        SSv[w] = SSv[w-1] - sc[w-1]*sc[w-1] + sc[w+4]*sc[w+4];
                        TTv[w] = TTv[w-1] - tc[w-1]*tc[w-1] + tc[w+4]*tc[w+4];
                    }
                    *(float4*)&rs[2][r][x4] = make_float4(SSv[0],SSv[1],SSv[2],SSv[3]);
                    *(float4*)&rs[3][r][x4] = make_float4(TTv[0],TTv[1],TTv[2],TTv[3]);
                }
                {
                    float ST0=0.f;
                    #pragma unroll
                    for (int j = 0; j < 5; j++) ST0 = fmaf(sc[j], tc[j], ST0);
                    float STv[4];
                    STv[0]=ST0;
                    #pragma unroll
                    for (int w = 1; w < 4; w++)
                        STv[w] = STv[w-1] - sc[w-1]*tc[w-1] + sc[w+4]*tc[w+4];
                    *(float4*)&rs[4][r][x4] = make_float4(STv[0],STv[1],STv[2],STv[3]);
                }
            }
            __syncthreads();                     // rs ready

            // ---- y-direction sums, 2 stacked pixels per thread ----
            float n0[5], n1[5];
            #pragma unroll
            for (int c = 0; c < 5; c++) {
                float v0 = rs[c][yb+0][tx];
                float v1 = rs[c][yb+1][tx];
                float v2 = rs[c][yb+2][tx];
                float v3 = rs[c][yb+3][tx];
                float v4 = rs[c][yb+4][tx];
                float v5 = rs[c][yb+5][tx];
                float sm = ((v0+v1)+(v2+v3))+v4;
                n0[c] = sm;
                n1[c] = sm - v0 + v5;
            }

            // ---- z-direction: incremental ring update (slot s compile-time) --
            #pragma unroll
            for (int c = 0; c < 5; c++) {
                run[0][c]    += n0[c] - ring[s][0][c];
                ring[s][0][c] = n0[c];
                run[1][c]    += n1[c] - ring[s][1][c];
                ring[s][1][c] = n1[c];
            }

            const int zo = zp - 2;
            if (zo >= z0 && zo < z0 + CHUNK) {
                const float inv = 1.f / 125.f;
                #pragma unroll
                for (int p = 0; p < 2; p++) {
                    float sm = run[p][0] * inv;
                    float tm = run[p][1] * inv;
                    float sv = fmaf(-sm, sm, run[p][2] * inv);
                    float tv = fmaf(-tm, tm, run[p][3] * inv);
                    float cr = fmaf(-sm, tm, run[p][4] * inv);
                    float den = fmaf(sv, tv, 1e-5f);
                    acc += __fdividef(cr * cr, den);
                }
            }
        }
    }

    // ---- block reduction ----
    #pragma unroll
    for (int o = 16; o > 0; o >>= 1)
        acc += __shfl_xor_sync(0xffffffffu, acc, o);
    if ((tid & 31) == 0) wsum[tid >> 5] = acc;
    __syncthreads();

    // ---- grid reduction + last-block finalize ----
    if (tid == 0) {
        float bsum = 0.f;
        #pragma unroll
        for (int i = 0; i < 8; i++) bsum += wsum[i];
        atomicAdd(&g_acc, (double)bsum);
        __threadfence();
        unsigned done = atomicAdd(&g_cnt, 1u);
        if (done == NBLOCKS - 1) {
            double total = atomicAdd(&g_acc, 0.0);  // fenced read
            const double n = 2.0 * 160.0 * 192.0 * 192.0;
            float loss = (float)(1.0 - total / n);
            if (isnan(loss) || isinf(loss)) loss = 1.0f;
            out[0] = loss;
            // reset for the next graph replay
            *((volatile double*)&g_acc)   = 0.0;
            *((volatile unsigned*)&g_cnt) = 0u;
        }
    }
}

extern "C" void kernel_launch(void* const* d_in, const int* in_sizes, int n_in,
                              void* d_out, int out_size)
{
    (void)in_sizes; (void)n_in; (void)out_size;
    const float* src = (const float*)d_in[0];
    const float* tgt = (const float*)d_in[1];

    lncc_k<<<dim3(W_ / 32, H_ / 16, 2 * (D_ / CHUNK)), dim3(32, 8)>>>(
        src, tgt, (float*)d_out);
}

// round 4
// speedup vs baseline: 2.2921x; 1.3128x over previous
#include <cuda_runtime.h>
#include <math.h>

#define W_ 192
#define H_ 192
#define D_ 160
#define CHUNK 80
#define NPLANES 84
#define NBLOCKS (6 * 12 * 4)

// named barrier ids
#define BAR_FULL0  1
#define BAR_FULL1  2
#define BAR_EMPTY0 3
#define BAR_EMPTY1 4
#define BAR_PROD   5

__device__ double   g_acc;
__device__ unsigned g_cnt;

__device__ __forceinline__ void bar_sync_n(int id, int cnt) {
    asm volatile("bar.sync %0, %1;" :: "r"(id), "r"(cnt) : "memory");
}
__device__ __forceinline__ void bar_arrive_n(int id, int cnt) {
    asm volatile("bar.arrive %0, %1;" :: "r"(id), "r"(cnt) : "memory");
}

__global__ void __launch_bounds__(512, 1)
lncc_k(const float* __restrict__ src, const float* __restrict__ tgt,
       float* __restrict__ out)
{
    // Producer-owned: double-buffered raw tile [buf][img][haloRow(20)][col(36 pad 40)]
    __shared__ float tile[2][2][20][40];
    // Handoff: double-buffered x-sums [buf][ch][haloRow(20)][x(32)]
    __shared__ float rs[2][5][20][32];
    __shared__ float wsum[16];

    const int tid = threadIdx.x;
    const int x0  = blockIdx.x * 32;
    const int y0  = blockIdx.y * 16;
    const int b   = blockIdx.z >> 1;
    const int z0  = (blockIdx.z & 1) * CHUNK;
    const int zstart = z0 - 2;

    const float* baseS = src + (size_t)b * (D_ * H_ * W_);
    const float* baseT = tgt + (size_t)b * (D_ * H_ * W_);

    float acc = 0.f;

    if (tid < 256) {
        // ============================ PRODUCER ============================
        const int tx = tid & 31;
        const int ty = tid >> 5;                  // 0..7

        // 6 load slots covering the 36x20 halo tile (rows ty+8k, cols tx+32m)
        int goff[6], soff[6];
        unsigned flags = 0;  // bit sl: gmem in-range; bit sl+8: slot used
        #pragma unroll
        for (int k = 0; k < 3; k++) {
            #pragma unroll
            for (int m = 0; m < 2; m++) {
                const int sl = k * 2 + m;
                goff[sl] = 0; soff[sl] = 0;
                const int r = ty + 8 * k;
                const int c = tx + 32 * m;
                const bool slotv = (r < 20) && (m == 0 || tx < 4);
                if (slotv) {
                    soff[sl] = r * 40 + c;
                    flags |= 1u << (sl + 8);
                    const int gy = y0 + r - 2;
                    const int gx = x0 + c - 2;
                    if ((unsigned)gy < (unsigned)H_ && (unsigned)gx < (unsigned)W_) {
                        flags |= 1u << sl;
                        goff[sl] = gy * W_ + gx;
                    }
                }
            }
        }

        float pfs[6], pft[6];
        auto issue_loads = [&](int zp) {
            const bool zin  = (zp >= 0) && (zp < D_);
            const int pbase = zp * (H_ * W_);
            #pragma unroll
            for (int sl = 0; sl < 6; sl++) {
                float vs = 0.f, vt = 0.f;
                if (zin && (flags & (1u << sl))) {
                    vs = __ldg(baseS + pbase + goff[sl]);
                    vt = __ldg(baseT + pbase + goff[sl]);
                }
                pfs[sl] = vs; pft[sl] = vt;
            }
        };

        issue_loads(zstart);

        for (int p = 0; p < NPLANES; p += 2) {
            #pragma unroll
            for (int q = 0; q < 2; q++) {        // q == buffer index (compile-time)
                const int ip = p + q;            // NPLANES even -> always < NPLANES
                const int zp = zstart + ip;

                // store plane ip into tile[q] (safe: tile[q] last read at ip-2,
                // fenced by BAR_PROD of iteration ip-1)
                {
                    float* tf = &tile[q][0][0][0];
                    #pragma unroll
                    for (int sl = 0; sl < 6; sl++)
                        if (flags & (1u << (sl + 8))) {
                            tf[soff[sl]]       = pfs[sl];
                            tf[800 + soff[sl]] = pft[sl];
                        }
                }
                issue_loads(zp + 1);             // prefetch next plane
                bar_sync_n(BAR_PROD, 256);       // tile[q] ready (producers only)
                // wait until consumers finished rs[q] of plane ip-2
                bar_sync_n(q ? BAR_EMPTY1 : BAR_EMPTY0, 512);

                // ---- x-direction sliding 5-tap sums: 20 rows x 8 groups ----
                if (tid < 160) {
                    const int r  = tid >> 3;
                    const int x4 = (tid & 7) << 2;
                    const float* rowS = &tile[q][0][r][x4];
                    const float* rowT = &tile[q][1][r][x4];
                    float4 a0 = *(const float4*)(rowS);
                    float4 a1 = *(const float4*)(rowS + 4);
                    float4 b0 = *(const float4*)(rowT);
                    float4 b1 = *(const float4*)(rowT + 4);
                    float sc[8] = {a0.x,a0.y,a0.z,a0.w,a1.x,a1.y,a1.z,a1.w};
                    float tc[8] = {b0.x,b0.y,b0.z,b0.w,b1.x,b1.y,b1.z,b1.w};

                    {
                        float S0=0.f, T0=0.f;
                        #pragma unroll
                        for (int j = 0; j < 5; j++) { S0 += sc[j]; T0 += tc[j]; }
                        float Sv[4], Tv[4];
                        Sv[0]=S0; Tv[0]=T0;
                        #pragma unroll
                        for (int w = 1; w < 4; w++) {
                            Sv[w] = Sv[w-1] - sc[w-1] + sc[w+4];
                            Tv[w] = Tv[w-1] - tc[w-1] + tc[w+4];
                        }
                        *(float4*)&rs[q][0][r][x4] = make_float4(Sv[0],Sv[1],Sv[2],Sv[3]);
                        *(float4*)&rs[q][1][r][x4] = make_float4(Tv[0],Tv[1],Tv[2],Tv[3]);
                    }
                    {
                        float SS0=0.f, TT0=0.f;
                        #pragma unroll
                        for (int j = 0; j < 5; j++) {
                            SS0 = fmaf(sc[j], sc[j], SS0);
                            TT0 = fmaf(tc[j], tc[j], TT0);
                        }
                        float SSv[4], TTv[4];
                        SSv[0]=SS0; TTv[0]=TT0;
                        #pragma unroll
                        for (int w = 1; w < 4; w++) {
                            SSv[w] = SSv[w-1] - sc[w-1]*sc[w-1] + sc[w+4]*sc[w+4];
                            TTv[w] = TTv[w-1] - tc[w-1]*tc[w-1] + tc[w+4]*tc[w+4];
                        }
                        *(float4*)&rs[q][2][r][x4] = make_float4(SSv[0],SSv[1],SSv[2],SSv[3]);
                        *(float4*)&rs[q][3][r][x4] = make_float4(TTv[0],TTv[1],TTv[2],TTv[3]);
                    }
                    {
                        float ST0=0.f;
                        #pragma unroll
                        for (int j = 0; j < 5; j++) ST0 = fmaf(sc[j], tc[j], ST0);
                        float STv[4];
                        STv[0]=ST0;
                        #pragma unroll
                        for (int w = 1; w < 4; w++)
                            STv[w] = STv[w-1] - sc[w-1]*tc[w-1] + sc[w+4]*tc[w+4];
                        *(float4*)&rs[q][4][r][x4] = make_float4(STv[0],STv[1],STv[2],STv[3]);
                    }
                }
                // publish rs[q] for plane ip
                bar_arrive_n(q ? BAR_FULL1 : BAR_FULL0, 512);
            }
        }
    } else {
        // ============================ CONSUMER ============================
        const int ctid = tid - 256;
        const int ctx  = ctid & 31;
        const int cty  = ctid >> 5;              // 0..7
        const int yb   = 2 * cty;

        float ring[5][2][5];
        float run[2][5];
        #pragma unroll
        for (int s = 0; s < 5; s++)
            #pragma unroll
            for (int pp = 0; pp < 2; pp++)
                #pragma unroll
                for (int c = 0; c < 5; c++) ring[s][pp][c] = 0.f;
        #pragma unroll
        for (int pp = 0; pp < 2; pp++)
            #pragma unroll
            for (int c = 0; c < 5; c++) run[pp][c] = 0.f;

        // prime both empty barriers so producers can fill rs[0], rs[1]
        bar_arrive_n(BAR_EMPTY0, 512);
        bar_arrive_n(BAR_EMPTY1, 512);

        for (int basep = 0; basep < NPLANES; basep += 10) {
            #pragma unroll
            for (int s2 = 0; s2 < 10; s2++) {    // s2: compile-time
                const int ip = basep + s2;
                if (ip >= NPLANES) break;        // 84 = 8*10 + 4
                const int s = s2 % 5;            // ring slot (compile-time)
                // wait for rs[s2&1] of plane ip
                bar_sync_n((s2 & 1) ? BAR_FULL1 : BAR_FULL0, 512);

                // ---- y-direction sums, 2 stacked pixels per thread ----
                float n0[5], n1[5];
                #pragma unroll
                for (int c = 0; c < 5; c++) {
                    float v0 = rs[s2 & 1][c][yb+0][ctx];
                    float v1 = rs[s2 & 1][c][yb+1][ctx];
                    float v2 = rs[s2 & 1][c][yb+2][ctx];
                    float v3 = rs[s2 & 1][c][yb+3][ctx];
                    float v4 = rs[s2 & 1][c][yb+4][ctx];
                    float v5 = rs[s2 & 1][c][yb+5][ctx];
                    float sm = ((v0 + v1) + (v2 + v3)) + v4;
                    n0[c] = sm;
                    n1[c] = sm - v0 + v5;
                }
                // release the buffer ASAP, then do private math (overlaps producer)
                bar_arrive_n((s2 & 1) ? BAR_EMPTY1 : BAR_EMPTY0, 512);

                #pragma unroll
                for (int c = 0; c < 5; c++) {
                    run[0][c]    += n0[c] - ring[s][0][c];
                    ring[s][0][c] = n0[c];
                    run[1][c]    += n1[c] - ring[s][1][c];
                    ring[s][1][c] = n1[c];
                }

                if (ip >= 4) {                   // zo = z0 + ip - 4 in range
                    const float inv = 1.f / 125.f;
                    #pragma unroll
                    for (int pp = 0; pp < 2; pp++) {
                        float sm = run[pp][0] * inv;
                        float tm = run[pp][1] * inv;
                        float sv = fmaf(-sm, sm, run[pp][2] * inv);
                        float tv = fmaf(-tm, tm, run[pp][3] * inv);
                        float cr = fmaf(-sm, tm, run[pp][4] * inv);
                        float den = fmaf(sv, tv, 1e-5f);
                        acc += __fdividef(cr * cr, den);
                    }
                }
            }
        }
    }

    // ---- block reduction over all 512 threads (producers contribute 0) ----
    __syncthreads();
    #pragma unroll
    for (int o = 16; o > 0; o >>= 1)
        acc += __shfl_xor_sync(0xffffffffu, acc, o);
    if ((tid & 31) == 0) wsum[tid >> 5] = acc;
    __syncthreads();

    if (tid == 0) {
        float bsum = 0.f;
        #pragma unroll
        for (int i = 0; i < 16; i++) bsum += wsum[i];
        atomicAdd(&g_acc, (double)bsum);
        __threadfence();
        unsigned done = atomicAdd(&g_cnt, 1u);
        if (done == NBLOCKS - 1) {
            double total = atomicAdd(&g_acc, 0.0);  // fenced read
            const double n = 2.0 * 160.0 * 192.0 * 192.0;
            float loss = (float)(1.0 - total / n);
            if (isnan(loss) || isinf(loss)) loss = 1.0f;
            out[0] = loss;
            // reset for the next graph replay
            *((volatile double*)&g_acc)   = 0.0;
            *((volatile unsigned*)&g_cnt) = 0u;
        }
    }
}

extern "C" void kernel_launch(void* const* d_in, const int* in_sizes, int n_in,
                              void* d_out, int out_size)
{
    (void)in_sizes; (void)n_in; (void)out_size;
    const float* src = (const float*)d_in[0];
    const float* tgt = (const float*)d_in[1];

    lncc_k<<<dim3(6, 12, 4), 512>>>(src, tgt, (float*)d_out);
}

// round 5
// speedup vs baseline: 3.1535x; 1.3758x over previous
#include <cuda_runtime.h>
#include <math.h>
#include <stdint.h>

#define W_ 192
#define H_ 192
#define D_ 160
#define HW_ (H_ * W_)
#define CHUNK 80
#define NPLANES 84
#define NBLOCKS (6 * 12 * 4)

#define BAR_FULL0  1
#define BAR_FULL1  2
#define BAR_EMPTY0 3
#define BAR_EMPTY1 4
#define BAR_PROD   5

__device__ double   g_acc;
__device__ unsigned g_cnt;

static __device__ __forceinline__ void bar_sync_n(int id, int cnt) {
    asm volatile("bar.sync %0, %1;" :: "r"(id), "r"(cnt) : "memory");
}
static __device__ __forceinline__ void bar_arrive_n(int id, int cnt) {
    asm volatile("bar.arrive %0, %1;" :: "r"(id), "r"(cnt) : "memory");
}
static __device__ __forceinline__ void cp_async8(uint32_t dst, const float* src,
                                                 unsigned srcsz) {
    asm volatile("cp.async.ca.shared.global [%0], [%1], 8, %2;"
                 :: "r"(dst), "l"(src), "r"(srcsz) : "memory");
}
static __device__ __forceinline__ void cp_commit() {
    asm volatile("cp.async.commit_group;" ::: "memory");
}
static __device__ __forceinline__ void cp_wait2() {
    asm volatile("cp.async.wait_group 2;" ::: "memory");
}

__global__ void __launch_bounds__(512, 1)
lncc_k(const float* __restrict__ src, const float* __restrict__ tgt,
       float* __restrict__ out)
{
    // Triple-buffered raw tile: [buf][img][haloRow(20)][col(36 pad 40)]
    __shared__ float tile[3][2][20][40];
    // Double-buffered x-sums: [buf][ch][haloRow(20)][x(32)]
    __shared__ float rs[2][5][20][32];
    __shared__ float wsum[16];

    const int tid = threadIdx.x;
    const int x0  = blockIdx.x * 32;
    const int y0  = blockIdx.y * 16;
    const int b   = blockIdx.z >> 1;
    const int z0  = (blockIdx.z & 1) * CHUNK;
    const int zstart = z0 - 2;

    const float* baseS = src + (size_t)b * (D_ * HW_);
    const float* baseT = tgt + (size_t)b * (D_ * HW_);

    float acc = 0.f;

    if (tid < 256) {
        // ============================ PRODUCER ============================
        // Halo tile 36 cols x 20 rows x 2 imgs = 720 8-byte pairs (18 pairs/row).
        // Slot sl covers pair index i = tid + 256*sl (sl=2 only for tid<208).
        uint32_t soffb[3];        // byte offset within one tile buffer
        const float* gbase[3];    // global pointer at z=0 (clamped when invalid)
        unsigned vmask = 0;       // bit sl: xy-valid
        const int nslot = (tid < 208) ? 3 : 2;
        #pragma unroll
        for (int sl = 0; sl < 3; sl++) {
            const int i   = tid + 256 * sl;
            const int img = (i >= 360) ? 1 : 0;
            const int j   = i - img * 360;
            const int row = j / 18;
            const int pc  = j - row * 18;
            soffb[sl] = (uint32_t)(img * 800 + row * 40 + pc * 2) * 4u;
            const int gy = y0 + row - 2;
            const int gx = x0 + pc * 2 - 2;      // even; pairs never straddle W
            const bool v = ((unsigned)gy < (unsigned)H_) &&
                           ((unsigned)gx < (unsigned)W_);
            if (v) vmask |= 1u << sl;
            gbase[sl] = (img ? baseT : baseS) + (v ? (gy * W_ + gx) : 0);
        }

        uint32_t sbase = (uint32_t)__cvta_generic_to_shared(&tile[0][0][0][0]);

        auto issue_plane = [&](int ip2, int buf) {
            const int zp  = zstart + ip2;
            const bool zin = (unsigned)zp < (unsigned)D_;
            const int zoff = zin ? zp * HW_ : 0;
            const uint32_t tb = sbase + (uint32_t)buf * 6400u;
            #pragma unroll
            for (int sl = 0; sl < 3; sl++) {
                if (sl < nslot) {
                    unsigned sz = (zin && (vmask & (1u << sl))) ? 8u : 0u;
                    cp_async8(tb + soffb[sl], gbase[sl] + zoff, sz);
                }
            }
            cp_commit();
        };

        // prologue: planes 0,1 into buffers 0,1
        issue_plane(0, 0);
        issue_plane(1, 1);
        int bw = 2;   // next buffer to write
        int br = 0;   // buffer to read this plane

        for (int ip = 0; ip < NPLANES; ip++) {
            const int q = ip & 1;
            // consumers done with rs[q] (plane ip-2); also fences all producers
            // past x-phase of plane ip-1, so tile[bw] is reusable.
            bar_sync_n(BAR_EMPTY0 + q, 512);
            issue_plane(ip + 2, bw);
            bw = (bw == 2) ? 0 : bw + 1;
            cp_wait2();                        // plane ip's group has landed
            bar_sync_n(BAR_PROD, 256);         // cross-thread visibility

            // ---- x-direction sliding 5-tap sums: 20 rows x 8 groups ----
            if (tid < 160) {
                const int r  = tid >> 3;
                const int x4 = (tid & 7) << 2;
                const float* rowS = &tile[br][0][r][x4];
                const float* rowT = &tile[br][1][r][x4];
                float* rsq = &rs[q][0][0][0];
                float4 a0 = *(const float4*)(rowS);
                float4 a1 = *(const float4*)(rowS + 4);
                float4 b0 = *(const float4*)(rowT);
                float4 b1 = *(const float4*)(rowT + 4);
                float sc[8] = {a0.x,a0.y,a0.z,a0.w,a1.x,a1.y,a1.z,a1.w};
                float tc[8] = {b0.x,b0.y,b0.z,b0.w,b1.x,b1.y,b1.z,b1.w};
                const int ro = r * 32 + x4;

                {
                    float S0=0.f, T0=0.f;
                    #pragma unroll
                    for (int j = 0; j < 5; j++) { S0 += sc[j]; T0 += tc[j]; }
                    float Sv[4], Tv[4];
                    Sv[0]=S0; Tv[0]=T0;
                    #pragma unroll
                    for (int w = 1; w < 4; w++) {
                        Sv[w] = Sv[w-1] - sc[w-1] + sc[w+4];
                        Tv[w] = Tv[w-1] - tc[w-1] + tc[w+4];
                    }
                    *(float4*)(rsq + 0*640 + ro) = make_float4(Sv[0],Sv[1],Sv[2],Sv[3]);
                    *(float4*)(rsq + 1*640 + ro) = make_float4(Tv[0],Tv[1],Tv[2],Tv[3]);
                }
                {
                    float SS0=0.f, TT0=0.f;
                    #pragma unroll
                    for (int j = 0; j < 5; j++) {
                        SS0 = fmaf(sc[j], sc[j], SS0);
                        TT0 = fmaf(tc[j], tc[j], TT0);
                    }
                    float SSv[4], TTv[4];
                    SSv[0]=SS0; TTv[0]=TT0;
                    #pragma unroll
                    for (int w = 1; w < 4; w++) {
                        SSv[w] = SSv[w-1] - sc[w-1]*sc[w-1] + sc[w+4]*sc[w+4];
                        TTv[w] = TTv[w-1] - tc[w-1]*tc[w-1] + tc[w+4]*tc[w+4];
                    }
                    *(float4*)(rsq + 2*640 + ro) = make_float4(SSv[0],SSv[1],SSv[2],SSv[3]);
                    *(float4*)(rsq + 3*640 + ro) = make_float4(TTv[0],TTv[1],TTv[2],TTv[3]);
                }
                {
                    float ST0=0.f;
                    #pragma unroll
                    for (int j = 0; j < 5; j++) ST0 = fmaf(sc[j], tc[j], ST0);
                    float STv[4];
                    STv[0]=ST0;
                    #pragma unroll
                    for (int w = 1; w < 4; w++)
                        STv[w] = STv[w-1] - sc[w-1]*tc[w-1] + sc[w+4]*tc[w+4];
                    *(float4*)(rsq + 4*640 + ro) = make_float4(STv[0],STv[1],STv[2],STv[3]);
                }
            }
            br = (br == 2) ? 0 : br + 1;
            bar_arrive_n(BAR_FULL0 + q, 512);  // rs[q] published for plane ip
        }
    } else {
        // ============================ CONSUMER ============================
        const int ctid = tid - 256;
        const int ctx  = ctid & 31;
        const int cty  = ctid >> 5;              // 0..7
        const int yb   = 2 * cty;

        float ring[5][2][5];
        float run[2][5];
        #pragma unroll
        for (int s = 0; s < 5; s++)
            #pragma unroll
            for (int pp = 0; pp < 2; pp++)
                #pragma unroll
                for (int c = 0; c < 5; c++) ring[s][pp][c] = 0.f;
        #pragma unroll
        for (int pp = 0; pp < 2; pp++)
            #pragma unroll
            for (int c = 0; c < 5; c++) run[pp][c] = 0.f;

        // prime both empty barriers so producers can fill rs[0], rs[1]
        bar_arrive_n(BAR_EMPTY0, 512);
        bar_arrive_n(BAR_EMPTY1, 512);

        for (int basep = 0; basep < NPLANES; basep += 10) {
            #pragma unroll
            for (int s2 = 0; s2 < 10; s2++) {    // compile-time ring/buf index
                const int ip = basep + s2;
                if (ip >= NPLANES) break;        // 84 = 8*10 + 4
                const int s = s2 % 5;
                bar_sync_n((s2 & 1) ? BAR_FULL1 : BAR_FULL0, 512);

                // ---- y-direction sums, 2 stacked pixels per thread ----
                float n0[5], n1[5];
                #pragma unroll
                for (int c = 0; c < 5; c++) {
                    float v0 = rs[s2 & 1][c][yb+0][ctx];
                    float v1 = rs[s2 & 1][c][yb+1][ctx];
                    float v2 = rs[s2 & 1][c][yb+2][ctx];
                    float v3 = rs[s2 & 1][c][yb+3][ctx];
                    float v4 = rs[s2 & 1][c][yb+4][ctx];
                    float v5 = rs[s2 & 1][c][yb+5][ctx];
                    float sm = ((v0 + v1) + (v2 + v3)) + v4;
                    n0[c] = sm;
                    n1[c] = sm - v0 + v5;
                }
                bar_arrive_n((s2 & 1) ? BAR_EMPTY1 : BAR_EMPTY0, 512);

                #pragma unroll
                for (int c = 0; c < 5; c++) {
                    run[0][c]    += n0[c] - ring[s][0][c];
                    ring[s][0][c] = n0[c];
                    run[1][c]    += n1[c] - ring[s][1][c];
                    ring[s][1][c] = n1[c];
                }

                if (ip >= 4) {
                    const float inv = 1.f / 125.f;
                    #pragma unroll
                    for (int pp = 0; pp < 2; pp++) {
                        float sm = run[pp][0] * inv;
                        float tm = run[pp][1] * inv;
                        float sv = fmaf(-sm, sm, run[pp][2] * inv);
                        float tv = fmaf(-tm, tm, run[pp][3] * inv);
                        float cr = fmaf(-sm, tm, run[pp][4] * inv);
                        float den = fmaf(sv, tv, 1e-5f);
                        acc += __fdividef(cr * cr, den);
                    }
                }
            }
        }
    }

    // ---- block reduction over all 512 threads (producers contribute 0) ----
    __syncthreads();
    #pragma unroll
    for (int o = 16; o > 0; o >>= 1)
        acc += __shfl_xor_sync(0xffffffffu, acc, o);
    if ((tid & 31) == 0) wsum[tid >> 5] = acc;
    __syncthreads();

    if (tid == 0) {
        float bsum = 0.f;
        #pragma unroll
        for (int i = 0; i < 16; i++) bsum += wsum[i];
        atomicAdd(&g_acc, (double)bsum);
        __threadfence();
        unsigned done = atomicAdd(&g_cnt, 1u);
        if (done == NBLOCKS - 1) {
            double total = atomicAdd(&g_acc, 0.0);  // fenced read
            const double n = 2.0 * 160.0 * 192.0 * 192.0;
            float loss = (float)(1.0 - total / n);
            if (isnan(loss) || isinf(loss)) loss = 1.0f;
            out[0] = loss;
            *((volatile double*)&g_acc)   = 0.0;
            *((volatile unsigned*)&g_cnt) = 0u;
        }
    }
}

extern "C" void kernel_launch(void* const* d_in, const int* in_sizes, int n_in,
                              void* d_out, int out_size)
{
    (void)in_sizes; (void)n_in; (void)out_size;
    const float* src = (const float*)d_in[0];
    const float* tgt = (const float*)d_in[1];

    lncc_k<<<dim3(6, 12, 4), 512>>>(src, tgt, (float*)d_out);
}